// round 9
// baseline (speedup 1.0000x reference)
#include <cuda_runtime.h>
#include <cuda_fp16.h>
#include <math.h>
#include <stdint.h>

#define BB 128
#define LL 256
#define NNB 8
#define FF 200
#define F3 600
#define BL (BB*LL)
#define RROUNDS 2
#define TSTEPS 2
#define KPAD 224
#define NCH 7

__device__ float g_molW[BB*FF];
__device__ float g_sst[BL*F3];
__device__ float g_gi[BL*F3];
__device__ float g_gh[BL*F3];
__device__ float g_dec[BL*64];
__device__ float g_decb[64];
__device__ float g_rb[RROUNDS*F3];

// fp16 split activation planes: hi at [0], lo at [APLANE]
#define APLANE ((size_t)BL*KPAD)
#define MPLANE ((size_t)BB*KPAD)
__device__ __align__(16) __half g_hsp[2*BL*KPAD];
__device__ __align__(16) __half g_asp[2*BL*KPAD];
__device__ __align__(16) __half g_csp[2*BL*KPAD];
__device__ __align__(16) __half g_mfsp[2*BB*KPAD];

// fp16 weight plane (hi only) [row][KPAD]
#define WROWS 5264
__device__ __align__(16) __half g_w[WROWS*KPAD];

#define W_MOL0 0
#define W_MOL1 200
#define W_MGI  400
#define W_MGH  1000
#define W_RND(d) (1600 + (d)*1800)
#define W_DEC  5200
#define NSEG 14

__device__ __forceinline__ uint32_t smem_u32(const void* p) {
    uint32_t a;
    asm("{ .reg .u64 t; cvta.to.shared.u64 t, %1; cvt.u32.u64 %0, t; }"
        : "=r"(a) : "l"(p));
    return a;
}
__device__ __forceinline__ void ldsm4(uint32_t* r, uint32_t a) {
    asm volatile("ldmatrix.sync.aligned.m8n8.x4.shared.b16 {%0,%1,%2,%3}, [%4];"
        : "=r"(r[0]), "=r"(r[1]), "=r"(r[2]), "=r"(r[3]) : "r"(a));
}
__device__ __forceinline__ void mma_f16(float* c, const uint32_t* a, const uint32_t* b) {
    asm volatile("mma.sync.aligned.m16n8k16.row.col.f32.f16.f16.f32 "
        "{%0,%1,%2,%3}, {%4,%5,%6,%7}, {%8,%9}, {%0,%1,%2,%3};"
        : "+f"(c[0]), "+f"(c[1]), "+f"(c[2]), "+f"(c[3])
        : "r"(a[0]), "r"(a[1]), "r"(a[2]), "r"(a[3]), "r"(b[0]), "r"(b[1]));
}
__device__ __forceinline__ void cpa16(uint32_t dst, const void* src, int srcSize) {
    asm volatile("cp.async.cg.shared.global [%0], [%1], 16, %2;"
        :: "r"(dst), "l"(src), "r"(srcSize));
}
__device__ __forceinline__ void cp_commit() {
    asm volatile("cp.async.commit_group;" ::: "memory");
}
__device__ __forceinline__ void cp_wait0() {
    asm volatile("cp.async.wait_group 0;" ::: "memory");
}
__device__ __forceinline__ void split2h(float v, __half* hi, __half* lo) {
    __half h = __float2half(v);
    *hi = h;
    *lo = __float2half(v - __half2float(h));
}

// ---- fused weight prep: 14 segments covering rows [0, W_DEC) ----
struct PrepSeg { const float* src; int stride; int dst; int pad; };
struct PrepTab { PrepSeg s[NSEG]; };

__global__ void prep_all(PrepTab tab)
{
    int idx = blockIdx.x * blockDim.x + threadIdx.x;
    if (idx >= W_DEC * KPAD) return;
    int r = idx / KPAD, k = idx - r * KPAD;
    int si = 0;
    #pragma unroll
    for (int i = 1; i < NSEG; i++) if (r >= tab.s[i].dst) si = i;
    const PrepSeg sg = tab.s[si];
    int lr = r - sg.dst;
    float x = (k < FF) ? sg.src[(size_t)lr * sg.stride + k] : 0.f;
    g_w[(size_t)r * KPAD + k] = __float2half(x);
}

// decode rows 5200..5258
__global__ void prep_dec(const float* __restrict__ afw,
                         const float* __restrict__ bfw)
{
    int idx = blockIdx.x * blockDim.x + threadIdx.x;
    if (idx >= 59 * KPAD) return;
    int r = idx / KPAD, k = idx - r * KPAD;
    float x = 0.f;
    if (k < FF) {
        if (r < 39)      x = afw[(size_t)r * FF + k];
        else if (r < 49) x = bfw[(size_t)(r - 39) * (2 * FF) + k];
        else             x = bfw[(size_t)(r - 49) * (2 * FF) + FF + k];
    }
    g_w[(size_t)(W_DEC + r) * KPAD + k] = __float2half(x);
}

__global__ void split_molf(const float* __restrict__ src)
{
    int idx = blockIdx.x * blockDim.x + threadIdx.x;
    if (idx >= BB * KPAD) return;
    int r = idx / KPAD, k = idx - r * KPAD;
    float x = (k < FF) ? src[(size_t)r * FF + k] : 0.f;
    split2h(x, &g_mfsp[idx], &g_mfsp[MPLANE + idx]);
}

__global__ void prep_misc(const float* __restrict__ ab, const float* __restrict__ bb,
                          const float* __restrict__ align_b, const float* __restrict__ attend_b)
{
    int i = blockIdx.x * blockDim.x + threadIdx.x;
    if (i < 64) {
        float v = 0.f;
        if (i < 39) v = ab[i];
        else if (i < 49) v = bb[i - 39];
        g_decb[i] = v;
    }
    int j = i - 64;
    if (j >= 0 && j < RROUNDS * F3) {
        int d = j / F3, f = j - d * F3;
        float v = 0.f;
        if (f < 200) v = align_b[d * FF + f];
        else if (f >= 400) v = attend_b[d * FF + f - 400];
        g_rb[j] = v;
    }
}

// ---- 2-pass fp16-split tensor GEMM: C = act((Ahi+Alo) @ Whi^T + ...) ----
#define PITCH 80
#define REG 10240            // 128 rows * PITCH
#define STG 30720            // 3 regions per stage: A_hi, A_lo, B
#define TG_SMEM (2*STG)      // 61440

template<int ACT, int OUT>
__global__ __launch_bounds__(256, 2) void tgemm(
    const __half* __restrict__ Ap, const __half* __restrict__ Wp,
    const float* __restrict__ bias, float* __restrict__ C,
    __half* __restrict__ Cp,
    int M, int Nn, const float* __restrict__ rowAdd, int rpg,
    long aOffB, long cOffE)
{
    extern __shared__ __align__(16) char sm[];
    const uint32_t sb = smem_u32(sm);
    const int tid = threadIdx.x, lane = tid & 31, wid = tid >> 5;
    const int bm = blockIdx.y * 128, bn = blockIdx.x * 128;
    const int wm = (wid & 3) * 32, wn = (wid >> 2) * 64;

    float acc[2][8][4];
    #pragma unroll
    for (int i = 0; i < 2; i++)
        #pragma unroll
        for (int j = 0; j < 8; j++)
            #pragma unroll
            for (int k = 0; k < 4; k++) acc[i][j][k] = 0.f;

    const int r0 = tid >> 2, q0 = (tid & 3) * 16;
    const int r1 = r0 + 64;
    const int n0 = bn + r0, n1 = bn + r1;
    const int v0 = (n0 < Nn) ? 16 : 0, v1 = (n1 < Nn) ? 16 : 0;
    const char* pA0 = (const char*)(Ap + (size_t)(bm + r0) * KPAD) + q0;
    const char* pA1 = (const char*)(Ap + (size_t)(bm + r1) * KPAD) + q0;
    const char* pB0 = (const char*)(Wp + (size_t)(v0 ? n0 : 0) * KPAD) + q0;
    const char* pB1 = (const char*)(Wp + (size_t)(v1 ? n1 : 0) * KPAD) + q0;
    const uint32_t d0 = (uint32_t)(r0 * PITCH) + q0;
    const uint32_t d1 = (uint32_t)(r1 * PITCH) + q0;

    auto stage_load = [&](int t, int st) {
        const int kb = t * 64;
        const uint32_t s = sb + st * STG;
        cpa16(s + d0,         pA0 + kb, 16);
        cpa16(s + d1,         pA1 + kb, 16);
        cpa16(s + REG + d0,   pA0 + aOffB + kb, 16);
        cpa16(s + REG + d1,   pA1 + aOffB + kb, 16);
        cpa16(s + 2*REG + d0, pB0 + kb, v0);
        cpa16(s + 2*REG + d1, pB1 + kb, v1);
    };

    stage_load(0, 0);
    cp_commit();

    const int arow = lane & 15;
    const int brow = lane & 7, sel = lane >> 3;
    const int nOff = (sel >> 1) * 8, kOff = (sel & 1) * 8;

    for (int t = 0; t < NCH; t++) {
        cp_wait0();
        __syncthreads();
        if (t + 1 < NCH) { stage_load(t + 1, (t + 1) & 1); cp_commit(); }
        const uint32_t s = sb + (t & 1) * STG;

        #pragma unroll
        for (int ks = 0; ks < 32; ks += 16) {
            uint32_t ah[2][4], al[2][4];
            const uint32_t akc = (uint32_t)(ks + ((lane >> 4) << 3)) * 2;
            #pragma unroll
            for (int mi = 0; mi < 2; mi++) {
                uint32_t ad = s + (uint32_t)(wm + mi * 16 + arow) * PITCH + akc;
                ldsm4(ah[mi], ad);
                ldsm4(al[mi], ad + REG);
            }
            #pragma unroll
            for (int half = 0; half < 2; half++) {
                uint32_t bh[2][4];
                #pragma unroll
                for (int p = 0; p < 2; p++) {
                    uint32_t bd = s + 2*REG
                        + (uint32_t)(wn + (half * 2 + p) * 16 + nOff + brow) * PITCH
                        + (uint32_t)(ks + kOff) * 2;
                    ldsm4(bh[p], bd);
                }
                #pragma unroll
                for (int mi = 0; mi < 2; mi++)
                    #pragma unroll
                    for (int nj = 0; nj < 4; nj++) {
                        const uint32_t* b2 = &bh[nj >> 1][(nj & 1) * 2];
                        float* a = acc[mi][half * 4 + nj];
                        mma_f16(a, ah[mi], b2);
                        mma_f16(a, al[mi], b2);
                    }
            }
        }
        __syncthreads();
    }

    const int lr = lane >> 2, lc = (lane & 3) * 2;
    #pragma unroll
    for (int mi = 0; mi < 2; mi++) {
        #pragma unroll
        for (int hh = 0; hh < 2; hh++) {
            int m = bm + wm + mi * 16 + hh * 8 + lr;
            const float* ra = rowAdd ? (rowAdd + (size_t)(m / rpg) * Nn) : nullptr;
            #pragma unroll
            for (int ni = 0; ni < 8; ni++) {
                int n = bn + wn + ni * 8 + lc;
                if (n >= Nn) continue;
                float v0f = acc[mi][ni][hh * 2 + 0];
                float v1f = acc[mi][ni][hh * 2 + 1];
                if (bias) { v0f += bias[n]; v1f += bias[n + 1]; }
                if (ra)   { v0f += ra[n];   v1f += ra[n + 1]; }
                if (ACT == 1) { v0f = (v0f > 0.f) ? v0f : expm1f(v0f);
                                v1f = (v1f > 0.f) ? v1f : expm1f(v1f); }
                else if (ACT == 2) { v0f = fmaxf(v0f, 0.f); v1f = fmaxf(v1f, 0.f); }
                if (OUT == 0) {
                    *(float2*)&C[(size_t)m * Nn + n] = make_float2(v0f, v1f);
                } else {
                    __half h0 = __float2half(v0f), h1 = __float2half(v1f);
                    __half l0 = __float2half(v0f - __half2float(h0));
                    __half l1 = __float2half(v1f - __half2float(h1));
                    size_t ci = (size_t)m * KPAD + n;
                    __half2 hh2; hh2.x = h0; hh2.y = h1;
                    __half2 ll2; ll2.x = l0; ll2.y = l1;
                    *(__half2*)&Cp[ci] = hh2;
                    *(__half2*)&Cp[cOffE + ci] = ll2;
                }
            }
        }
    }
}

__global__ __launch_bounds__(256) void mol_pre_kernel(
    const float* __restrict__ molf, const float* __restrict__ actf)
{
    int b = blockIdx.x;
    int tid = threadIdx.x;
    __shared__ float dots[LL];
    __shared__ float red[16];
    const float* mf = molf + (size_t)b * FF;
    int lane = tid & 31, warp = tid >> 5;

    for (int l = warp; l < LL; l += 8) {
        const float* af = actf + ((size_t)b * LL + l) * FF;
        float s = 0.f;
        for (int f = lane; f < FF; f += 32) s += mf[f] * af[f];
        #pragma unroll
        for (int o = 16; o > 0; o >>= 1) s += __shfl_xor_sync(0xffffffffu, s, o);
        if (lane == 0) dots[l] = s;
    }
    __syncthreads();

    float v = dots[tid];
    float m = v;
    #pragma unroll
    for (int o = 16; o > 0; o >>= 1) m = fmaxf(m, __shfl_xor_sync(0xffffffffu, m, o));
    if (lane == 0) red[warp] = m;
    __syncthreads();
    float mx = red[0];
    #pragma unroll
    for (int i = 1; i < 8; i++) mx = fmaxf(mx, red[i]);
    float e = expf(v - mx);
    float s = e;
    #pragma unroll
    for (int o = 16; o > 0; o >>= 1) s += __shfl_xor_sync(0xffffffffu, s, o);
    if (lane == 0) red[8 + warp] = s;
    __syncthreads();
    float tot = 0.f;
    #pragma unroll
    for (int i = 0; i < 8; i++) tot += red[8 + i];
    __syncthreads();
    dots[tid] = e / tot;
    __syncthreads();

    size_t base = (size_t)b * LL * FF;
    for (int i = tid; i < LL * FF; i += 256) {
        int l = i / FF, f = i - l * FF;
        float v2 = dots[l] * mf[f] + actf[base + i];
        size_t si = ((size_t)b * LL + l) * KPAD + f;
        split2h(v2, &g_hsp[si], &g_hsp[APLANE + si]);
    }
}

__global__ __launch_bounds__(256) void gru_combine_kernel(
    const float* __restrict__ gi, const float* __restrict__ gh,
    const __half* __restrict__ hsp, int writeH, int total)
{
    int idx = blockIdx.x * blockDim.x + threadIdx.x;
    if (idx >= total) return;
    int m = idx / FF, f = idx - m * FF;
    size_t b3 = (size_t)m * F3;
    float ir = gi[b3 + f], iz = gi[b3 + FF + f], in_ = gi[b3 + 2 * FF + f];
    float hr = gh[b3 + f], hz = gh[b3 + FF + f], hn = gh[b3 + 2 * FF + f];
    float r = 1.f / (1.f + expf(-(ir + hr)));
    float z = 1.f / (1.f + expf(-(iz + hz)));
    float n = tanhf(in_ + r * hn);
    size_t si = (size_t)m * KPAD + f;
    float h = __half2float(hsp[si]) + __half2float(hsp[APLANE + si]);
    float o = (1.f - z) * n + z * h;
    if (writeH) split2h(o, &g_hsp[si], &g_hsp[APLANE + si]);
    float a = fmaxf(o, 0.f);
    split2h(a, &g_asp[si], &g_asp[APLANE + si]);
}

__global__ __launch_bounds__(256) void attn_ctx_kernel(
    const float* __restrict__ sst, const int* __restrict__ deg)
{
    int bl = blockIdx.x;
    int b = bl >> 8;
    int tid = threadIdx.x;
    __shared__ int sidx[NNB];
    if (tid < NNB) sidx[tid] = deg[(size_t)bl * NNB + tid];
    __syncthreads();
    if (tid >= FF) return;
    int f = tid;
    float s1v = sst[(size_t)bl * F3 + f];
    float sc[NNB];
    float mx = -3.4e38f;
    #pragma unroll
    for (int n = 0; n < NNB; n++) {
        int j = sidx[n];
        float v = s1v + sst[((size_t)b * LL + j) * F3 + 200 + f];
        v = (v >= 0.f) ? v : 0.01f * v;
        if (j == LL - 1) v += -9e8f;
        sc[n] = v;
        mx = fmaxf(mx, v);
    }
    float sum = 0.f;
    #pragma unroll
    for (int n = 0; n < NNB; n++) { sc[n] = expf(sc[n] - mx); sum += sc[n]; }
    float inv = 1.f / sum;
    float c = 0.f;
    #pragma unroll
    for (int n = 0; n < NNB; n++) {
        int j = sidx[n];
        if (j != LL - 1)
            c += sc[n] * inv * sst[((size_t)b * LL + j) * F3 + 400 + f];
    }
    c = (c > 0.f) ? c : expm1f(c);
    size_t si = (size_t)bl * KPAD + f;
    split2h(c, &g_csp[si], &g_csp[APLANE + si]);
}

__device__ __forceinline__ void seg_softmax_acc(const float* v, float* y, int lo, int hi) {
    float m = -3.4e38f;
    for (int i = lo; i < hi; i++) m = fmaxf(m, v[i]);
    float s = 0.f;
    for (int i = lo; i < hi; i++) s += expf(v[i] - m);
    float inv = 1.f / s;
    for (int i = lo; i < hi; i++) y[i] += expf(v[i] - m) * inv;
}
__device__ __forceinline__ float sigf(float x) { return 1.f / (1.f + expf(-x)); }

__global__ __launch_bounds__(256) void atom_act_kernel(
    const float* __restrict__ dec, float* __restrict__ out, int rows)
{
    int m = blockIdx.x * blockDim.x + threadIdx.x;
    if (m >= rows) return;
    const float* x = dec + (size_t)m * 64;
    float v[39], y[39];
    #pragma unroll
    for (int i = 0; i < 39; i++) { v[i] = x[i]; y[i] = 0.f; }
    seg_softmax_acc(v, y, 0, 16);
    seg_softmax_acc(v, y, 16, 22);
    seg_softmax_acc(v, y, 24, 30);
    seg_softmax_acc(v, y, 31, 36);
    y[24] += fmaxf(v[24], 0.f);
    y[30] += sigf(v[30]);
    y[36] += sigf(v[36]);
    y[37] += sigf(v[37]);
    y[38] += sigf(v[38]);
    float* o = out + (size_t)m * 39;
    #pragma unroll
    for (int i = 0; i < 39; i++) o[i] = y[i];
}

__global__ __launch_bounds__(256) void bond_act_kernel(
    const float* __restrict__ dec, const int* __restrict__ deg,
    float* __restrict__ out, int total)
{
    int id = blockIdx.x * blockDim.x + threadIdx.x;
    if (id >= total) return;
    int bl = id / NNB;
    int b = bl >> 8;
    int j = deg[id];
    const float* a = dec + (size_t)bl * 64 + 39;
    const float* c = dec + ((size_t)b * LL + j) * 64 + 49;
    float v[10], y[10];
    #pragma unroll
    for (int k = 0; k < 10; k++) { v[k] = a[k] + c[k]; y[k] = 0.f; }
    seg_softmax_acc(v, y, 0, 4);
    seg_softmax_acc(v, y, 6, 10);
    y[4] += sigf(v[4]);
    y[5] += sigf(v[5]);
    float* o = out + (size_t)id * 10;
    #pragma unroll
    for (int k = 0; k < 10; k++) o[k] = y[k];
}

static inline dim3 tg_grid(int M, int N) {
    return dim3((N + 127) / 128, M / 128);
}

extern "C" void kernel_launch(void* const* d_in, const int* in_sizes, int n_in,
                              void* d_out, int out_size)
{
    const int*   deg        = (const int*)  d_in[2];
    const float* molf       = (const float*)d_in[5];
    const float* actf       = (const float*)d_in[6];
    const float* atom_fc_w  = (const float*)d_in[7];
    const float* atom_fc_b  = (const float*)d_in[8];
    const float* bond_fc_w  = (const float*)d_in[9];
    const float* bond_fc_b  = (const float*)d_in[10];
    const float* align_w    = (const float*)d_in[11];
    const float* align_b    = (const float*)d_in[12];
    const float* attend_w   = (const float*)d_in[13];
    const float* attend_b   = (const float*)d_in[14];
    const float* gru_wih    = (const float*)d_in[15];
    const float* gru_whh    = (const float*)d_in[16];
    const float* gru_bih    = (const float*)d_in[17];
    const float* gru_bhh    = (const float*)d_in[18];
    const float* mol_al_w   = (const float*)d_in[19];
    const float* mol_al_b   = (const float*)d_in[20];
    const float* mgru_wih   = (const float*)d_in[21];
    const float* mgru_whh   = (const float*)d_in[22];
    const float* mgru_bih   = (const float*)d_in[23];
    const float* mgru_bhh   = (const float*)d_in[24];
    float* out = (float*)d_out;

    float *p_molW, *p_sst, *p_gi, *p_gh, *p_dec, *p_decb, *p_rb;
    __half *p_w, *p_h, *p_a, *p_c, *p_mf;
    cudaGetSymbolAddress((void**)&p_molW, g_molW);
    cudaGetSymbolAddress((void**)&p_sst,  g_sst);
    cudaGetSymbolAddress((void**)&p_gi,   g_gi);
    cudaGetSymbolAddress((void**)&p_gh,   g_gh);
    cudaGetSymbolAddress((void**)&p_dec,  g_dec);
    cudaGetSymbolAddress((void**)&p_decb, g_decb);
    cudaGetSymbolAddress((void**)&p_rb,   g_rb);
    cudaGetSymbolAddress((void**)&p_w,    g_w);
    cudaGetSymbolAddress((void**)&p_h,    g_hsp);
    cudaGetSymbolAddress((void**)&p_a,    g_asp);
    cudaGetSymbolAddress((void**)&p_c,    g_csp);
    cudaGetSymbolAddress((void**)&p_mf,   g_mfsp);

    cudaFuncSetAttribute(tgemm<0,0>, cudaFuncAttributeMaxDynamicSharedMemorySize, TG_SMEM);
    cudaFuncSetAttribute(tgemm<1,1>, cudaFuncAttributeMaxDynamicSharedMemorySize, TG_SMEM);

    const long AOB = (long)(APLANE * 2);   // bytes to lo plane (half = 2B)
    const long MOB = (long)(MPLANE * 2);

    {
        PrepTab tab;
        int i = 0;
        auto add = [&](const float* s, int st, int dst) {
            tab.s[i].src = s; tab.s[i].stride = st; tab.s[i].dst = dst; tab.s[i].pad = 0; i++;
        };
        add(mol_al_w,      2*FF, W_MOL0);
        add(mol_al_w + FF, 2*FF, W_MOL1);
        add(mgru_wih,      FF,   W_MGI);
        add(mgru_whh,      FF,   W_MGH);
        for (int d = 0; d < RROUNDS; d++) {
            const float* aw = align_w + (size_t)d * FF * 2 * FF;
            add(aw,                             2*FF, W_RND(d) + 0);
            add(aw + FF,                        2*FF, W_RND(d) + 200);
            add(attend_w + (size_t)d * FF * FF, FF,   W_RND(d) + 400);
            add(gru_wih + (size_t)d * F3 * FF,  FF,   W_RND(d) + 600);
            add(gru_whh + (size_t)d * F3 * FF,  FF,   W_RND(d) + 1200);
        }
        prep_all<<<(W_DEC * KPAD + 255) / 256, 256>>>(tab);
    }
    prep_dec<<<(59 * KPAD + 255) / 256, 256>>>(atom_fc_w, bond_fc_w);
    prep_misc<<<(64 + RROUNDS * F3 + 255) / 256, 256>>>(atom_fc_b, bond_fc_b, align_b, attend_b);
    split_molf<<<(BB * KPAD + 255) / 256, 256>>>(molf);

    #define WOFFP(o) (p_w + (size_t)(o) * KPAD)

    mol_pre_kernel<<<BB, 256>>>(molf, actf);

    tgemm<0,0><<<tg_grid(BB, FF), 256, TG_SMEM>>>(
        p_mf, WOFFP(W_MOL0), mol_al_b, p_molW, nullptr,
        BB, FF, nullptr, 1, MOB, 0);

    for (int t = 0; t < TSTEPS; t++) {
        tgemm<1,1><<<tg_grid(BL, FF), 256, TG_SMEM>>>(
            p_h, WOFFP(W_MOL1), nullptr, nullptr, p_c,
            BL, FF, p_molW, LL, AOB, (long)APLANE);
        tgemm<0,0><<<tg_grid(BL, F3), 256, TG_SMEM>>>(
            p_c, WOFFP(W_MGI), mgru_bih, p_gi, nullptr,
            BL, F3, nullptr, 1, AOB, 0);
        tgemm<0,0><<<tg_grid(BL, F3), 256, TG_SMEM>>>(
            p_h, WOFFP(W_MGH), mgru_bhh, p_gh, nullptr,
            BL, F3, nullptr, 1, AOB, 0);
        gru_combine_kernel<<<(BL * FF + 255) / 256, 256>>>(p_gi, p_gh, p_h, 1, BL * FF);
    }

    for (int d = 0; d < RROUNDS; d++) {
        tgemm<0,0><<<tg_grid(BL, F3), 256, TG_SMEM>>>(
            p_a, WOFFP(W_RND(d)), p_rb + (size_t)d * F3, p_sst, nullptr,
            BL, F3, nullptr, 1, AOB, 0);
        attn_ctx_kernel<<<BL, 256>>>(p_sst, deg);
        tgemm<0,0><<<tg_grid(BL, F3), 256, TG_SMEM>>>(
            p_c, WOFFP(W_RND(d) + 600), gru_bih + (size_t)d * F3, p_gi, nullptr,
            BL, F3, nullptr, 1, AOB, 0);
        tgemm<0,0><<<tg_grid(BL, F3), 256, TG_SMEM>>>(
            p_a, WOFFP(W_RND(d) + 1200), gru_bhh + (size_t)d * F3, p_gh, nullptr,
            BL, F3, nullptr, 1, AOB, 0);
        gru_combine_kernel<<<(BL * FF + 255) / 256, 256>>>(p_gi, p_gh, p_a, 0, BL * FF);
    }

    tgemm<0,0><<<tg_grid(BL, 64), 256, TG_SMEM>>>(
        p_a, WOFFP(W_DEC), p_decb, p_dec, nullptr,
        BL, 64, nullptr, 1, AOB, 0);

    atom_act_kernel<<<(BL + 255) / 256, 256>>>(p_dec, out, BL);
    bond_act_kernel<<<(BL * NNB + 255) / 256, 256>>>(p_dec, deg,
                                                     out + (size_t)BL * 39, BL * NNB);
}

// round 10
// speedup vs baseline: 1.2248x; 1.2248x over previous
#include <cuda_runtime.h>
#include <cuda_bf16.h>
#include <math.h>
#include <stdint.h>

#define BB 128
#define LL 256
#define NNB 8
#define FF 200
#define F3 600
#define BL (BB*LL)
#define RROUNDS 2
#define TSTEPS 2
#define KPAD 224
#define NCH 7

__device__ float g_molW[BB*FF];
__device__ float g_sst[BL*F3];
__device__ float g_gi[BL*F3];
__device__ float g_gh[BL*F3];
__device__ float g_dec[BL*64];
__device__ float g_decb[64];
__device__ float g_rb[RROUNDS*F3];

#define APLANE ((size_t)BL*KPAD)
#define MPLANE ((size_t)BB*KPAD)
__device__ __align__(16) __nv_bfloat16 g_hsp[2*BL*KPAD];
__device__ __align__(16) __nv_bfloat16 g_asp[2*BL*KPAD];
__device__ __align__(16) __nv_bfloat16 g_csp[2*BL*KPAD];
__device__ __align__(16) __nv_bfloat16 g_mfsp[2*BB*KPAD];

#define WROWS 5264
#define WPLANE ((size_t)WROWS*KPAD)
__device__ __align__(16) __nv_bfloat16 g_wsp[2*WROWS*KPAD];

#define W_MOL0 0
#define W_MOL1 200
#define W_MGI  400
#define W_MGH  1000
#define W_RND(d) (1600 + (d)*1800)
#define W_DEC  5200
#define NSEG 14

__device__ __forceinline__ uint32_t smem_u32(const void* p) {
    uint32_t a;
    asm("{ .reg .u64 t; cvta.to.shared.u64 t, %1; cvt.u32.u64 %0, t; }"
        : "=r"(a) : "l"(p));
    return a;
}
__device__ __forceinline__ void ldsm4(uint32_t* r, uint32_t a) {
    asm volatile("ldmatrix.sync.aligned.m8n8.x4.shared.b16 {%0,%1,%2,%3}, [%4];"
        : "=r"(r[0]), "=r"(r[1]), "=r"(r[2]), "=r"(r[3]) : "r"(a));
}
__device__ __forceinline__ void mma_bf16(float* c, const uint32_t* a, const uint32_t* b) {
    asm volatile("mma.sync.aligned.m16n8k16.row.col.f32.bf16.bf16.f32 "
        "{%0,%1,%2,%3}, {%4,%5,%6,%7}, {%8,%9}, {%0,%1,%2,%3};"
        : "+f"(c[0]), "+f"(c[1]), "+f"(c[2]), "+f"(c[3])
        : "r"(a[0]), "r"(a[1]), "r"(a[2]), "r"(a[3]), "r"(b[0]), "r"(b[1]));
}
__device__ __forceinline__ void cpa16(uint32_t dst, const void* src, int srcSize) {
    asm volatile("cp.async.cg.shared.global [%0], [%1], 16, %2;"
        :: "r"(dst), "l"(src), "r"(srcSize));
}
__device__ __forceinline__ void cp_commit() {
    asm volatile("cp.async.commit_group;" ::: "memory");
}
__device__ __forceinline__ void cp_wait0() {
    asm volatile("cp.async.wait_group 0;" ::: "memory");
}
__device__ __forceinline__ void split2(float v, __nv_bfloat16* hi, __nv_bfloat16* lo) {
    __nv_bfloat16 h = __float2bfloat16(v);
    *hi = h;
    *lo = __float2bfloat16(v - __bfloat162float(h));
}

// ---- fused weight prep: 14 segments covering rows [0, W_DEC) ----
struct PrepSeg { const float* src; int stride; int dst; int pad; };
struct PrepTab { PrepSeg s[NSEG]; };

__global__ void prep_all(PrepTab tab)
{
    int idx = blockIdx.x * blockDim.x + threadIdx.x;
    if (idx >= W_DEC * KPAD) return;
    int r = idx / KPAD, k = idx - r * KPAD;
    int si = 0;
    #pragma unroll
    for (int i = 1; i < NSEG; i++) if (r >= tab.s[i].dst) si = i;
    const PrepSeg sg = tab.s[si];
    int lr = r - sg.dst;
    float x = (k < FF) ? sg.src[(size_t)lr * sg.stride + k] : 0.f;
    split2(x, &g_wsp[(size_t)r * KPAD + k], &g_wsp[WPLANE + (size_t)r * KPAD + k]);
}

// everything else small: decode weight rows, biases, molf split — one kernel
#define REST_DEC (59*KPAD)
#define REST_MISC (64 + RROUNDS*F3)
#define REST_MOLF (BB*KPAD)
#define REST_TOT (REST_DEC + REST_MISC + REST_MOLF)

__global__ void prep_rest(const float* __restrict__ afw, const float* __restrict__ bfw,
                          const float* __restrict__ ab,  const float* __restrict__ bb,
                          const float* __restrict__ align_b, const float* __restrict__ attend_b,
                          const float* __restrict__ molf)
{
    int idx = blockIdx.x * blockDim.x + threadIdx.x;
    if (idx < REST_DEC) {
        int r = idx / KPAD, k = idx - r * KPAD;
        float x = 0.f;
        if (k < FF) {
            if (r < 39)      x = afw[(size_t)r * FF + k];
            else if (r < 49) x = bfw[(size_t)(r - 39) * (2 * FF) + k];
            else             x = bfw[(size_t)(r - 49) * (2 * FF) + FF + k];
        }
        size_t rr = (size_t)(W_DEC + r) * KPAD + k;
        split2(x, &g_wsp[rr], &g_wsp[WPLANE + rr]);
        return;
    }
    idx -= REST_DEC;
    if (idx < REST_MISC) {
        if (idx < 64) {
            float v = 0.f;
            if (idx < 39) v = ab[idx];
            else if (idx < 49) v = bb[idx - 39];
            g_decb[idx] = v;
        } else {
            int j = idx - 64;
            int d = j / F3, f = j - d * F3;
            float v = 0.f;
            if (f < 200) v = align_b[d * FF + f];
            else if (f >= 400) v = attend_b[d * FF + f - 400];
            g_rb[j] = v;
        }
        return;
    }
    idx -= REST_MISC;
    {
        int r = idx / KPAD, k = idx - r * KPAD;
        float x = (k < FF) ? molf[(size_t)r * FF + k] : 0.f;
        split2(x, &g_mfsp[idx], &g_mfsp[MPLANE + idx]);
    }
}

// ---- split-bf16 tensor GEMM (3-pass), optional dual problem via blockIdx.z ----
#define PITCH 80
#define REG 10240
#define STG 40960
#define TG_SMEM (2*STG)

template<int ACT, int OUT>
__global__ __launch_bounds__(256, 2) void tgemm(
    const __nv_bfloat16* __restrict__ Ap0, const __nv_bfloat16* __restrict__ Wp0,
    const float* __restrict__ bias0, float* __restrict__ C0,
    __nv_bfloat16* __restrict__ Cp,
    int M, int Nn, const float* __restrict__ rowAdd, int rpg,
    long aOffB, long wOffB, long cOffE,
    const __nv_bfloat16* Ap1, const __nv_bfloat16* Wp1,
    const float* bias1, float* C1)
{
    extern __shared__ __align__(16) char sm[];
    const uint32_t sb = smem_u32(sm);
    const int tid = threadIdx.x, lane = tid & 31, wid = tid >> 5;
    const int bm = blockIdx.y * 128, bn = blockIdx.x * 128;
    const int wm = (wid & 3) * 32, wn = (wid >> 2) * 64;

    const __nv_bfloat16* Ap = Ap0;
    const __nv_bfloat16* Wp = Wp0;
    const float* bias = bias0;
    float* C = C0;
    if (blockIdx.z == 1) { Ap = Ap1; Wp = Wp1; bias = bias1; C = C1; }

    float acc[2][8][4];
    #pragma unroll
    for (int i = 0; i < 2; i++)
        #pragma unroll
        for (int j = 0; j < 8; j++)
            #pragma unroll
            for (int k = 0; k < 4; k++) acc[i][j][k] = 0.f;

    const int r0 = tid >> 2, q0 = (tid & 3) * 16;
    const int r1 = r0 + 64;
    const int n0 = bn + r0, n1 = bn + r1;
    const int v0 = (n0 < Nn) ? 16 : 0, v1 = (n1 < Nn) ? 16 : 0;
    const char* pA0 = (const char*)(Ap + (size_t)(bm + r0) * KPAD) + q0;
    const char* pA1 = (const char*)(Ap + (size_t)(bm + r1) * KPAD) + q0;
    const char* pB0 = (const char*)(Wp + (size_t)(v0 ? n0 : 0) * KPAD) + q0;
    const char* pB1 = (const char*)(Wp + (size_t)(v1 ? n1 : 0) * KPAD) + q0;
    const uint32_t d0 = (uint32_t)(r0 * PITCH) + q0;
    const uint32_t d1 = (uint32_t)(r1 * PITCH) + q0;

    auto stage_load = [&](int t, int st) {
        const int kb = t * 64;
        const uint32_t s = sb + st * STG;
        cpa16(s + d0,         pA0 + kb, 16);
        cpa16(s + d1,         pA1 + kb, 16);
        cpa16(s + REG + d0,   pA0 + aOffB + kb, 16);
        cpa16(s + REG + d1,   pA1 + aOffB + kb, 16);
        cpa16(s + 2*REG + d0, pB0 + kb, v0);
        cpa16(s + 2*REG + d1, pB1 + kb, v1);
        cpa16(s + 3*REG + d0, pB0 + wOffB + kb, v0);
        cpa16(s + 3*REG + d1, pB1 + wOffB + kb, v1);
    };

    stage_load(0, 0);
    cp_commit();

    const int arow = lane & 15;
    const int brow = lane & 7, sel = lane >> 3;
    const int nOff = (sel >> 1) * 8, kOff = (sel & 1) * 8;

    for (int t = 0; t < NCH; t++) {
        cp_wait0();
        __syncthreads();
        if (t + 1 < NCH) { stage_load(t + 1, (t + 1) & 1); cp_commit(); }
        const uint32_t s = sb + (t & 1) * STG;

        #pragma unroll
        for (int ks = 0; ks < 32; ks += 16) {
            uint32_t ah[2][4], al[2][4];
            const uint32_t akc = (uint32_t)(ks + ((lane >> 4) << 3)) * 2;
            #pragma unroll
            for (int mi = 0; mi < 2; mi++) {
                uint32_t ad = s + (uint32_t)(wm + mi * 16 + arow) * PITCH + akc;
                ldsm4(ah[mi], ad);
                ldsm4(al[mi], ad + REG);
            }
            #pragma unroll
            for (int half = 0; half < 2; half++) {
                uint32_t bh[2][4], blo[2][4];
                #pragma unroll
                for (int p = 0; p < 2; p++) {
                    uint32_t bd = s + 2*REG
                        + (uint32_t)(wn + (half * 2 + p) * 16 + nOff + brow) * PITCH
                        + (uint32_t)(ks + kOff) * 2;
                    ldsm4(bh[p], bd);
                    ldsm4(blo[p], bd + REG);
                }
                #pragma unroll
                for (int mi = 0; mi < 2; mi++)
                    #pragma unroll
                    for (int nj = 0; nj < 4; nj++) {
                        const uint32_t* b2h = &bh[nj >> 1][(nj & 1) * 2];
                        const uint32_t* b2l = &blo[nj >> 1][(nj & 1) * 2];
                        float* a = acc[mi][half * 4 + nj];
                        mma_bf16(a, ah[mi], b2h);
                        mma_bf16(a, ah[mi], b2l);
                        mma_bf16(a, al[mi], b2h);
                    }
            }
        }
        __syncthreads();
    }

    const int lr = lane >> 2, lc = (lane & 3) * 2;
    #pragma unroll
    for (int mi = 0; mi < 2; mi++) {
        #pragma unroll
        for (int hh = 0; hh < 2; hh++) {
            int m = bm + wm + mi * 16 + hh * 8 + lr;
            const float* ra = rowAdd ? (rowAdd + (size_t)(m / rpg) * Nn) : nullptr;
            #pragma unroll
            for (int ni = 0; ni < 8; ni++) {
                int n = bn + wn + ni * 8 + lc;
                if (n >= Nn) continue;
                float v0f = acc[mi][ni][hh * 2 + 0];
                float v1f = acc[mi][ni][hh * 2 + 1];
                if (bias) { v0f += bias[n]; v1f += bias[n + 1]; }
                if (ra)   { v0f += ra[n];   v1f += ra[n + 1]; }
                if (ACT == 1) { v0f = (v0f > 0.f) ? v0f : expm1f(v0f);
                                v1f = (v1f > 0.f) ? v1f : expm1f(v1f); }
                else if (ACT == 2) { v0f = fmaxf(v0f, 0.f); v1f = fmaxf(v1f, 0.f); }
                if (OUT == 0) {
                    *(float2*)&C[(size_t)m * Nn + n] = make_float2(v0f, v1f);
                } else {
                    __nv_bfloat162 h2 = __floats2bfloat162_rn(v0f, v1f);
                    __nv_bfloat162 l2 = __floats2bfloat162_rn(
                        v0f - __bfloat162float(h2.x), v1f - __bfloat162float(h2.y));
                    size_t ci = (size_t)m * KPAD + n;
                    *(__nv_bfloat162*)&Cp[ci] = h2;
                    *(__nv_bfloat162*)&Cp[cOffE + ci] = l2;
                }
            }
        }
    }
}

__global__ __launch_bounds__(256) void mol_pre_kernel(
    const float* __restrict__ molf, const float* __restrict__ actf)
{
    int b = blockIdx.x;
    int tid = threadIdx.x;
    __shared__ float dots[LL];
    __shared__ float red[16];
    const float* mf = molf + (size_t)b * FF;
    int lane = tid & 31, warp = tid >> 5;

    for (int l = warp; l < LL; l += 8) {
        const float* af = actf + ((size_t)b * LL + l) * FF;
        float s = 0.f;
        for (int f = lane; f < FF; f += 32) s += mf[f] * af[f];
        #pragma unroll
        for (int o = 16; o > 0; o >>= 1) s += __shfl_xor_sync(0xffffffffu, s, o);
        if (lane == 0) dots[l] = s;
    }
    __syncthreads();

    float v = dots[tid];
    float m = v;
    #pragma unroll
    for (int o = 16; o > 0; o >>= 1) m = fmaxf(m, __shfl_xor_sync(0xffffffffu, m, o));
    if (lane == 0) red[warp] = m;
    __syncthreads();
    float mx = red[0];
    #pragma unroll
    for (int i = 1; i < 8; i++) mx = fmaxf(mx, red[i]);
    float e = expf(v - mx);
    float s = e;
    #pragma unroll
    for (int o = 16; o > 0; o >>= 1) s += __shfl_xor_sync(0xffffffffu, s, o);
    if (lane == 0) red[8 + warp] = s;
    __syncthreads();
    float tot = 0.f;
    #pragma unroll
    for (int i = 0; i < 8; i++) tot += red[8 + i];
    __syncthreads();
    dots[tid] = e / tot;
    __syncthreads();

    size_t base = (size_t)b * LL * FF;
    for (int i = tid; i < LL * FF; i += 256) {
        int l = i / FF, f = i - l * FF;
        float v2 = dots[l] * mf[f] + actf[base + i];
        size_t si = ((size_t)b * LL + l) * KPAD + f;
        split2(v2, &g_hsp[si], &g_hsp[APLANE + si]);
    }
}

__global__ __launch_bounds__(256) void gru_combine_kernel(
    const float* __restrict__ gi, const float* __restrict__ gh,
    const __nv_bfloat16* __restrict__ hsp, int writeH, int total)
{
    int idx = blockIdx.x * blockDim.x + threadIdx.x;
    if (idx >= total) return;
    int m = idx / FF, f = idx - m * FF;
    size_t b3 = (size_t)m * F3;
    float ir = gi[b3 + f], iz = gi[b3 + FF + f], in_ = gi[b3 + 2 * FF + f];
    float hr = gh[b3 + f], hz = gh[b3 + FF + f], hn = gh[b3 + 2 * FF + f];
    float r = 1.f / (1.f + expf(-(ir + hr)));
    float z = 1.f / (1.f + expf(-(iz + hz)));
    float n = tanhf(in_ + r * hn);
    size_t si = (size_t)m * KPAD + f;
    float h = __bfloat162float(hsp[si]) + __bfloat162float(hsp[APLANE + si]);
    float o = (1.f - z) * n + z * h;
    if (writeH) split2(o, &g_hsp[si], &g_hsp[APLANE + si]);
    float a = fmaxf(o, 0.f);
    split2(a, &g_asp[si], &g_asp[APLANE + si]);
}

__global__ __launch_bounds__(256) void attn_ctx_kernel(
    const float* __restrict__ sst, const int* __restrict__ deg)
{
    int bl = blockIdx.x;
    int b = bl >> 8;
    int tid = threadIdx.x;
    __shared__ int sidx[NNB];
    if (tid < NNB) sidx[tid] = deg[(size_t)bl * NNB + tid];
    __syncthreads();
    if (tid >= FF) return;
    int f = tid;
    float s1v = sst[(size_t)bl * F3 + f];
    float sc[NNB];
    float mx = -3.4e38f;
    #pragma unroll
    for (int n = 0; n < NNB; n++) {
        int j = sidx[n];
        float v = s1v + sst[((size_t)b * LL + j) * F3 + 200 + f];
        v = (v >= 0.f) ? v : 0.01f * v;
        if (j == LL - 1) v += -9e8f;
        sc[n] = v;
        mx = fmaxf(mx, v);
    }
    float sum = 0.f;
    #pragma unroll
    for (int n = 0; n < NNB; n++) { sc[n] = expf(sc[n] - mx); sum += sc[n]; }
    float inv = 1.f / sum;
    float c = 0.f;
    #pragma unroll
    for (int n = 0; n < NNB; n++) {
        int j = sidx[n];
        if (j != LL - 1)
            c += sc[n] * inv * sst[((size_t)b * LL + j) * F3 + 400 + f];
    }
    c = (c > 0.f) ? c : expm1f(c);
    size_t si = (size_t)bl * KPAD + f;
    split2(c, &g_csp[si], &g_csp[APLANE + si]);
}

__device__ __forceinline__ void seg_softmax_acc(const float* v, float* y, int lo, int hi) {
    float m = -3.4e38f;
    for (int i = lo; i < hi; i++) m = fmaxf(m, v[i]);
    float s = 0.f;
    for (int i = lo; i < hi; i++) s += expf(v[i] - m);
    float inv = 1.f / s;
    for (int i = lo; i < hi; i++) y[i] += expf(v[i] - m) * inv;
}
__device__ __forceinline__ float sigf(float x) { return 1.f / (1.f + expf(-x)); }

__global__ __launch_bounds__(256) void atom_act_kernel(
    const float* __restrict__ dec, float* __restrict__ out, int rows)
{
    int m = blockIdx.x * blockDim.x + threadIdx.x;
    if (m >= rows) return;
    const float* x = dec + (size_t)m * 64;
    float v[39], y[39];
    #pragma unroll
    for (int i = 0; i < 39; i++) { v[i] = x[i]; y[i] = 0.f; }
    seg_softmax_acc(v, y, 0, 16);
    seg_softmax_acc(v, y, 16, 22);
    seg_softmax_acc(v, y, 24, 30);
    seg_softmax_acc(v, y, 31, 36);
    y[24] += fmaxf(v[24], 0.f);
    y[30] += sigf(v[30]);
    y[36] += sigf(v[36]);
    y[37] += sigf(v[37]);
    y[38] += sigf(v[38]);
    float* o = out + (size_t)m * 39;
    #pragma unroll
    for (int i = 0; i < 39; i++) o[i] = y[i];
}

__global__ __launch_bounds__(256) void bond_act_kernel(
    const float* __restrict__ dec, const int* __restrict__ deg,
    float* __restrict__ out, int total)
{
    int id = blockIdx.x * blockDim.x + threadIdx.x;
    if (id >= total) return;
    int bl = id / NNB;
    int b = bl >> 8;
    int j = deg[id];
    const float* a = dec + (size_t)bl * 64 + 39;
    const float* c = dec + ((size_t)b * LL + j) * 64 + 49;
    float v[10], y[10];
    #pragma unroll
    for (int k = 0; k < 10; k++) { v[k] = a[k] + c[k]; y[k] = 0.f; }
    seg_softmax_acc(v, y, 0, 4);
    seg_softmax_acc(v, y, 6, 10);
    y[4] += sigf(v[4]);
    y[5] += sigf(v[5]);
    float* o = out + (size_t)id * 10;
    #pragma unroll
    for (int k = 0; k < 10; k++) o[k] = y[k];
}

static inline dim3 tg_grid(int M, int N, int z = 1) {
    return dim3((N + 127) / 128, M / 128, z);
}

extern "C" void kernel_launch(void* const* d_in, const int* in_sizes, int n_in,
                              void* d_out, int out_size)
{
    const int*   deg        = (const int*)  d_in[2];
    const float* molf       = (const float*)d_in[5];
    const float* actf       = (const float*)d_in[6];
    const float* atom_fc_w  = (const float*)d_in[7];
    const float* atom_fc_b  = (const float*)d_in[8];
    const float* bond_fc_w  = (const float*)d_in[9];
    const float* bond_fc_b  = (const float*)d_in[10];
    const float* align_w    = (const float*)d_in[11];
    const float* align_b    = (const float*)d_in[12];
    const float* attend_w   = (const float*)d_in[13];
    const float* attend_b   = (const float*)d_in[14];
    const float* gru_wih    = (const float*)d_in[15];
    const float* gru_whh    = (const float*)d_in[16];
    const float* gru_bih    = (const float*)d_in[17];
    const float* gru_bhh    = (const float*)d_in[18];
    const float* mol_al_w   = (const float*)d_in[19];
    const float* mol_al_b   = (const float*)d_in[20];
    const float* mgru_wih   = (const float*)d_in[21];
    const float* mgru_whh   = (const float*)d_in[22];
    const float* mgru_bih   = (const float*)d_in[23];
    const float* mgru_bhh   = (const float*)d_in[24];
    float* out = (float*)d_out;

    float *p_molW, *p_sst, *p_gi, *p_gh, *p_dec, *p_decb, *p_rb;
    __nv_bfloat16 *p_w, *p_h, *p_a, *p_c, *p_mf;
    cudaGetSymbolAddress((void**)&p_molW, g_molW);
    cudaGetSymbolAddress((void**)&p_sst,  g_sst);
    cudaGetSymbolAddress((void**)&p_gi,   g_gi);
    cudaGetSymbolAddress((void**)&p_gh,   g_gh);
    cudaGetSymbolAddress((void**)&p_dec,  g_dec);
    cudaGetSymbolAddress((void**)&p_decb, g_decb);
    cudaGetSymbolAddress((void**)&p_rb,   g_rb);
    cudaGetSymbolAddress((void**)&p_w,    g_wsp);
    cudaGetSymbolAddress((void**)&p_h,    g_hsp);
    cudaGetSymbolAddress((void**)&p_a,    g_asp);
    cudaGetSymbolAddress((void**)&p_c,    g_csp);
    cudaGetSymbolAddress((void**)&p_mf,   g_mfsp);

    cudaFuncSetAttribute(tgemm<0,0>, cudaFuncAttributeMaxDynamicSharedMemorySize, TG_SMEM);
    cudaFuncSetAttribute(tgemm<1,1>, cudaFuncAttributeMaxDynamicSharedMemorySize, TG_SMEM);

    const long AOB = (long)(APLANE * 2);
    const long MOB = (long)(MPLANE * 2);
    const long WOB = (long)(WPLANE * 2);

    // launch 0: bulk weight prep
    {
        PrepTab tab;
        int i = 0;
        auto add = [&](const float* s, int st, int dst) {
            tab.s[i].src = s; tab.s[i].stride = st; tab.s[i].dst = dst; tab.s[i].pad = 0; i++;
        };
        add(mol_al_w,      2*FF, W_MOL0);
        add(mol_al_w + FF, 2*FF, W_MOL1);
        add(mgru_wih,      FF,   W_MGI);
        add(mgru_whh,      FF,   W_MGH);
        for (int d = 0; d < RROUNDS; d++) {
            const float* aw = align_w + (size_t)d * FF * 2 * FF;
            add(aw,                             2*FF, W_RND(d) + 0);
            add(aw + FF,                        2*FF, W_RND(d) + 200);
            add(attend_w + (size_t)d * FF * FF, FF,   W_RND(d) + 400);
            add(gru_wih + (size_t)d * F3 * FF,  FF,   W_RND(d) + 600);
            add(gru_whh + (size_t)d * F3 * FF,  FF,   W_RND(d) + 1200);
        }
        prep_all<<<(W_DEC * KPAD + 255) / 256, 256>>>(tab);
    }
    // launch 1: all remaining prep
    prep_rest<<<(REST_TOT + 255) / 256, 256>>>(atom_fc_w, bond_fc_w,
                                               atom_fc_b, bond_fc_b,
                                               align_b, attend_b, molf);
    // launch 2
    mol_pre_kernel<<<BB, 256>>>(molf, actf);

    #define WOFFP(o) (p_w + (size_t)(o) * KPAD)
    #define NODUAL nullptr, nullptr, nullptr, nullptr

    // launch 3: molW (tiny)
    tgemm<0,0><<<tg_grid(BB, FF), 256, TG_SMEM>>>(
        p_mf, WOFFP(W_MOL0), mol_al_b, p_molW, nullptr,
        BB, FF, nullptr, 1, MOB, WOB, 0, NODUAL);

    for (int t = 0; t < TSTEPS; t++) {
        // launch 4 (first iter): ctx
        tgemm<1,1><<<tg_grid(BL, FF), 256, TG_SMEM>>>(
            p_h, WOFFP(W_MOL1), nullptr, nullptr, p_c,
            BL, FF, p_molW, LL, AOB, WOB, (long)APLANE, NODUAL);
        // launch 5 (first iter): dual gi+gh  <-- ncu -s 5 captures this
        tgemm<0,0><<<tg_grid(BL, F3, 2), 256, TG_SMEM>>>(
            p_c, WOFFP(W_MGI), mgru_bih, p_gi, nullptr,
            BL, F3, nullptr, 1, AOB, WOB, 0,
            p_h, WOFFP(W_MGH), mgru_bhh, p_gh);
        gru_combine_kernel<<<(BL * FF + 255) / 256, 256>>>(p_gi, p_gh, p_h, 1, BL * FF);
    }

    for (int d = 0; d < RROUNDS; d++) {
        tgemm<0,0><<<tg_grid(BL, F3), 256, TG_SMEM>>>(
            p_a, WOFFP(W_RND(d)), p_rb + (size_t)d * F3, p_sst, nullptr,
            BL, F3, nullptr, 1, AOB, WOB, 0, NODUAL);
        attn_ctx_kernel<<<BL, 256>>>(p_sst, deg);
        tgemm<0,0><<<tg_grid(BL, F3, 2), 256, TG_SMEM>>>(
            p_c, WOFFP(W_RND(d) + 600), gru_bih + (size_t)d * F3, p_gi, nullptr,
            BL, F3, nullptr, 1, AOB, WOB, 0,
            p_a, WOFFP(W_RND(d) + 1200), gru_bhh + (size_t)d * F3, p_gh);
        gru_combine_kernel<<<(BL * FF + 255) / 256, 256>>>(p_gi, p_gh, p_a, 0, BL * FF);
    }

    tgemm<0,0><<<tg_grid(BL, 64), 256, TG_SMEM>>>(
        p_a, WOFFP(W_DEC), p_decb, p_dec, nullptr,
        BL, 64, nullptr, 1, AOB, WOB, 0, NODUAL);

    atom_act_kernel<<<(BL + 255) / 256, 256>>>(p_dec, out, BL);
    bond_act_kernel<<<(BL * NNB + 255) / 256, 256>>>(p_dec, deg,
                                                     out + (size_t)BL * 39, BL * NNB);
}

// round 11
// speedup vs baseline: 1.2382x; 1.0109x over previous
#include <cuda_runtime.h>
#include <cuda_bf16.h>
#include <math.h>
#include <stdint.h>

#define BB 128
#define LL 256
#define NNB 8
#define FF 200
#define F3 600
#define BL (BB*LL)
#define RROUNDS 2
#define TSTEPS 2
#define KPAD 224
#define NCH 7

__device__ float g_molW[BB*FF];
__device__ float g_sst[BL*F3];
__device__ float g_gi[BL*F3];
__device__ float g_gh[BL*F3];
__device__ float g_dec[BL*64];
__device__ float g_decb[64];
__device__ float g_rb[RROUNDS*F3];

#define APLANE ((size_t)BL*KPAD)
#define MPLANE ((size_t)BB*KPAD)
__device__ __align__(16) __nv_bfloat16 g_hsp[2*BL*KPAD];
__device__ __align__(16) __nv_bfloat16 g_asp[2*BL*KPAD];
__device__ __align__(16) __nv_bfloat16 g_csp[2*BL*KPAD];
__device__ __align__(16) __nv_bfloat16 g_mfsp[2*BB*KPAD];

#define WROWS 5264
#define WPLANE ((size_t)WROWS*KPAD)
__device__ __align__(16) __nv_bfloat16 g_wsp[2*WROWS*KPAD];

#define W_MOL0 0
#define W_MOL1 200
#define W_MGI  400
#define W_MGH  1000
#define W_RND(d) (1600 + (d)*1800)
#define W_DEC  5200
#define NSEG 14

__device__ __forceinline__ uint32_t smem_u32(const void* p) {
    uint32_t a;
    asm("{ .reg .u64 t; cvta.to.shared.u64 t, %1; cvt.u32.u64 %0, t; }"
        : "=r"(a) : "l"(p));
    return a;
}
__device__ __forceinline__ void ldsm4(uint32_t* r, uint32_t a) {
    asm volatile("ldmatrix.sync.aligned.m8n8.x4.shared.b16 {%0,%1,%2,%3}, [%4];"
        : "=r"(r[0]), "=r"(r[1]), "=r"(r[2]), "=r"(r[3]) : "r"(a));
}
__device__ __forceinline__ void mma_bf16(float* c, const uint32_t* a, const uint32_t* b) {
    asm volatile("mma.sync.aligned.m16n8k16.row.col.f32.bf16.bf16.f32 "
        "{%0,%1,%2,%3}, {%4,%5,%6,%7}, {%8,%9}, {%0,%1,%2,%3};"
        : "+f"(c[0]), "+f"(c[1]), "+f"(c[2]), "+f"(c[3])
        : "r"(a[0]), "r"(a[1]), "r"(a[2]), "r"(a[3]), "r"(b[0]), "r"(b[1]));
}
__device__ __forceinline__ void cpa16(uint32_t dst, const void* src, int srcSize) {
    asm volatile("cp.async.cg.shared.global [%0], [%1], 16, %2;"
        :: "r"(dst), "l"(src), "r"(srcSize));
}
__device__ __forceinline__ void cp_commit() {
    asm volatile("cp.async.commit_group;" ::: "memory");
}
__device__ __forceinline__ void cp_wait0() {
    asm volatile("cp.async.wait_group 0;" ::: "memory");
}
__device__ __forceinline__ void split2(float v, __nv_bfloat16* hi, __nv_bfloat16* lo) {
    __nv_bfloat16 h = __float2bfloat16(v);
    *hi = h;
    *lo = __float2bfloat16(v - __bfloat162float(h));
}

// ---- fused weight prep: 14 segments covering rows [0, W_DEC) ----
struct PrepSeg { const float* src; int stride; int dst; int pad; };
struct PrepTab { PrepSeg s[NSEG]; };

__global__ void prep_all(PrepTab tab)
{
    int idx = blockIdx.x * blockDim.x + threadIdx.x;
    if (idx >= W_DEC * KPAD) return;
    int r = idx / KPAD, k = idx - r * KPAD;
    int si = 0;
    #pragma unroll
    for (int i = 1; i < NSEG; i++) if (r >= tab.s[i].dst) si = i;
    const PrepSeg sg = tab.s[si];
    int lr = r - sg.dst;
    float x = (k < FF) ? sg.src[(size_t)lr * sg.stride + k] : 0.f;
    split2(x, &g_wsp[(size_t)r * KPAD + k], &g_wsp[WPLANE + (size_t)r * KPAD + k]);
}

// everything else small: decode weight rows, biases, molf split — one kernel
#define REST_DEC (59*KPAD)
#define REST_MISC (64 + RROUNDS*F3)
#define REST_MOLF (BB*KPAD)
#define REST_TOT (REST_DEC + REST_MISC + REST_MOLF)

__global__ void prep_rest(const float* __restrict__ afw, const float* __restrict__ bfw,
                          const float* __restrict__ ab,  const float* __restrict__ bb,
                          const float* __restrict__ align_b, const float* __restrict__ attend_b,
                          const float* __restrict__ molf)
{
    int idx = blockIdx.x * blockDim.x + threadIdx.x;
    if (idx < REST_DEC) {
        int r = idx / KPAD, k = idx - r * KPAD;
        float x = 0.f;
        if (k < FF) {
            if (r < 39)      x = afw[(size_t)r * FF + k];
            else if (r < 49) x = bfw[(size_t)(r - 39) * (2 * FF) + k];
            else             x = bfw[(size_t)(r - 49) * (2 * FF) + FF + k];
        }
        size_t rr = (size_t)(W_DEC + r) * KPAD + k;
        split2(x, &g_wsp[rr], &g_wsp[WPLANE + rr]);
        return;
    }
    idx -= REST_DEC;
    if (idx < REST_MISC) {
        if (idx < 64) {
            float v = 0.f;
            if (idx < 39) v = ab[idx];
            else if (idx < 49) v = bb[idx - 39];
            g_decb[idx] = v;
        } else {
            int j = idx - 64;
            int d = j / F3, f = j - d * F3;
            float v = 0.f;
            if (f < 200) v = align_b[d * FF + f];
            else if (f >= 400) v = attend_b[d * FF + f - 400];
            g_rb[j] = v;
        }
        return;
    }
    idx -= REST_MISC;
    {
        int r = idx / KPAD, k = idx - r * KPAD;
        float x = (k < FF) ? molf[(size_t)r * FF + k] : 0.f;
        split2(x, &g_mfsp[idx], &g_mfsp[MPLANE + idx]);
    }
}

// ---- split-bf16 tensor GEMM (3-pass), optional dual problem via blockIdx.z ----
#define PITCH 80
#define REG 10240
#define STG 40960
#define TG_SMEM (2*STG)

template<int ACT, int OUT>
__global__ __launch_bounds__(256, 2) void tgemm(
    const __nv_bfloat16* __restrict__ Ap0, const __nv_bfloat16* __restrict__ Wp0,
    const float* __restrict__ bias0, float* __restrict__ C0,
    __nv_bfloat16* __restrict__ Cp,
    int M, int Nn, const float* __restrict__ rowAdd, int rpg,
    long aOffB, long wOffB, long cOffE,
    const __nv_bfloat16* Ap1, const __nv_bfloat16* Wp1,
    const float* bias1, float* C1)
{
    extern __shared__ __align__(16) char sm[];
    const uint32_t sb = smem_u32(sm);
    const int tid = threadIdx.x, lane = tid & 31, wid = tid >> 5;
    const int bm = blockIdx.y * 128, bn = blockIdx.x * 128;
    const int wm = (wid & 3) * 32, wn = (wid >> 2) * 64;

    const __nv_bfloat16* Ap = Ap0;
    const __nv_bfloat16* Wp = Wp0;
    const float* bias = bias0;
    float* C = C0;
    if (blockIdx.z == 1) { Ap = Ap1; Wp = Wp1; bias = bias1; C = C1; }

    float acc[2][8][4];
    #pragma unroll
    for (int i = 0; i < 2; i++)
        #pragma unroll
        for (int j = 0; j < 8; j++)
            #pragma unroll
            for (int k = 0; k < 4; k++) acc[i][j][k] = 0.f;

    const int r0 = tid >> 2, q0 = (tid & 3) * 16;
    const int r1 = r0 + 64;
    const int n0 = bn + r0, n1 = bn + r1;
    const int v0 = (n0 < Nn) ? 16 : 0, v1 = (n1 < Nn) ? 16 : 0;
    const char* pA0 = (const char*)(Ap + (size_t)(bm + r0) * KPAD) + q0;
    const char* pA1 = (const char*)(Ap + (size_t)(bm + r1) * KPAD) + q0;
    const char* pB0 = (const char*)(Wp + (size_t)(v0 ? n0 : 0) * KPAD) + q0;
    const char* pB1 = (const char*)(Wp + (size_t)(v1 ? n1 : 0) * KPAD) + q0;
    const uint32_t d0 = (uint32_t)(r0 * PITCH) + q0;
    const uint32_t d1 = (uint32_t)(r1 * PITCH) + q0;

    auto stage_load = [&](int t, int st) {
        const int kb = t * 64;
        const uint32_t s = sb + st * STG;
        cpa16(s + d0,         pA0 + kb, 16);
        cpa16(s + d1,         pA1 + kb, 16);
        cpa16(s + REG + d0,   pA0 + aOffB + kb, 16);
        cpa16(s + REG + d1,   pA1 + aOffB + kb, 16);
        cpa16(s + 2*REG + d0, pB0 + kb, v0);
        cpa16(s + 2*REG + d1, pB1 + kb, v1);
        cpa16(s + 3*REG + d0, pB0 + wOffB + kb, v0);
        cpa16(s + 3*REG + d1, pB1 + wOffB + kb, v1);
    };

    stage_load(0, 0);
    cp_commit();

    const int arow = lane & 15;
    const int brow = lane & 7, sel = lane >> 3;
    const int nOff = (sel >> 1) * 8, kOff = (sel & 1) * 8;

    for (int t = 0; t < NCH; t++) {
        cp_wait0();
        __syncthreads();
        if (t + 1 < NCH) { stage_load(t + 1, (t + 1) & 1); cp_commit(); }
        const uint32_t s = sb + (t & 1) * STG;

        #pragma unroll
        for (int ks = 0; ks < 32; ks += 16) {
            uint32_t ah[2][4], al[2][4];
            const uint32_t akc = (uint32_t)(ks + ((lane >> 4) << 3)) * 2;
            #pragma unroll
            for (int mi = 0; mi < 2; mi++) {
                uint32_t ad = s + (uint32_t)(wm + mi * 16 + arow) * PITCH + akc;
                ldsm4(ah[mi], ad);
                ldsm4(al[mi], ad + REG);
            }
            #pragma unroll
            for (int half = 0; half < 2; half++) {
                uint32_t bh[2][4], blo[2][4];
                #pragma unroll
                for (int p = 0; p < 2; p++) {
                    uint32_t bd = s + 2*REG
                        + (uint32_t)(wn + (half * 2 + p) * 16 + nOff + brow) * PITCH
                        + (uint32_t)(ks + kOff) * 2;
                    ldsm4(bh[p], bd);
                    ldsm4(blo[p], bd + REG);
                }
                #pragma unroll
                for (int mi = 0; mi < 2; mi++)
                    #pragma unroll
                    for (int nj = 0; nj < 4; nj++) {
                        const uint32_t* b2h = &bh[nj >> 1][(nj & 1) * 2];
                        const uint32_t* b2l = &blo[nj >> 1][(nj & 1) * 2];
                        float* a = acc[mi][half * 4 + nj];
                        mma_bf16(a, ah[mi], b2h);
                        mma_bf16(a, ah[mi], b2l);
                        mma_bf16(a, al[mi], b2h);
                    }
            }
        }
        __syncthreads();
    }

    const int lr = lane >> 2, lc = (lane & 3) * 2;
    #pragma unroll
    for (int mi = 0; mi < 2; mi++) {
        #pragma unroll
        for (int hh = 0; hh < 2; hh++) {
            int m = bm + wm + mi * 16 + hh * 8 + lr;
            const float* ra = rowAdd ? (rowAdd + (size_t)(m / rpg) * Nn) : nullptr;
            #pragma unroll
            for (int ni = 0; ni < 8; ni++) {
                int n = bn + wn + ni * 8 + lc;
                if (n >= Nn) continue;
                float v0f = acc[mi][ni][hh * 2 + 0];
                float v1f = acc[mi][ni][hh * 2 + 1];
                if (bias) { v0f += bias[n]; v1f += bias[n + 1]; }
                if (ra)   { v0f += ra[n];   v1f += ra[n + 1]; }
                if (ACT == 1) { v0f = (v0f > 0.f) ? v0f : expm1f(v0f);
                                v1f = (v1f > 0.f) ? v1f : expm1f(v1f); }
                else if (ACT == 2) { v0f = fmaxf(v0f, 0.f); v1f = fmaxf(v1f, 0.f); }
                if (OUT == 0) {
                    *(float2*)&C[(size_t)m * Nn + n] = make_float2(v0f, v1f);
                } else {
                    __nv_bfloat162 h2 = __floats2bfloat162_rn(v0f, v1f);
                    __nv_bfloat162 l2 = __floats2bfloat162_rn(
                        v0f - __bfloat162float(h2.x), v1f - __bfloat162float(h2.y));
                    size_t ci = (size_t)m * KPAD + n;
                    *(__nv_bfloat162*)&Cp[ci] = h2;
                    *(__nv_bfloat162*)&Cp[cOffE + ci] = l2;
                }
            }
        }
    }
}

__global__ __launch_bounds__(256) void mol_pre_kernel(
    const float* __restrict__ molf, const float* __restrict__ actf)
{
    int b = blockIdx.x;
    int tid = threadIdx.x;
    __shared__ float dots[LL];
    __shared__ float red[16];
    const float* mf = molf + (size_t)b * FF;
    int lane = tid & 31, warp = tid >> 5;

    for (int l = warp; l < LL; l += 8) {
        const float* af = actf + ((size_t)b * LL + l) * FF;
        float s = 0.f;
        for (int f = lane; f < FF; f += 32) s += mf[f] * af[f];
        #pragma unroll
        for (int o = 16; o > 0; o >>= 1) s += __shfl_xor_sync(0xffffffffu, s, o);
        if (lane == 0) dots[l] = s;
    }
    __syncthreads();

    float v = dots[tid];
    float m = v;
    #pragma unroll
    for (int o = 16; o > 0; o >>= 1) m = fmaxf(m, __shfl_xor_sync(0xffffffffu, m, o));
    if (lane == 0) red[warp] = m;
    __syncthreads();
    float mx = red[0];
    #pragma unroll
    for (int i = 1; i < 8; i++) mx = fmaxf(mx, red[i]);
    float e = expf(v - mx);
    float s = e;
    #pragma unroll
    for (int o = 16; o > 0; o >>= 1) s += __shfl_xor_sync(0xffffffffu, s, o);
    if (lane == 0) red[8 + warp] = s;
    __syncthreads();
    float tot = 0.f;
    #pragma unroll
    for (int i = 0; i < 8; i++) tot += red[8 + i];
    __syncthreads();
    dots[tid] = e / tot;
    __syncthreads();

    size_t base = (size_t)b * LL * FF;
    for (int i = tid; i < LL * FF; i += 256) {
        int l = i / FF, f = i - l * FF;
        float v2 = dots[l] * mf[f] + actf[base + i];
        size_t si = ((size_t)b * LL + l) * KPAD + f;
        split2(v2, &g_hsp[si], &g_hsp[APLANE + si]);
    }
}

__global__ __launch_bounds__(256) void gru_combine_kernel(
    const float* __restrict__ gi, const float* __restrict__ gh,
    const __nv_bfloat16* __restrict__ hsp, int writeH, int total)
{
    int idx = blockIdx.x * blockDim.x + threadIdx.x;
    if (idx >= total) return;
    int m = idx / FF, f = idx - m * FF;
    size_t b3 = (size_t)m * F3;
    float ir = gi[b3 + f], iz = gi[b3 + FF + f], in_ = gi[b3 + 2 * FF + f];
    float hr = gh[b3 + f], hz = gh[b3 + FF + f], hn = gh[b3 + 2 * FF + f];
    float r = 1.f / (1.f + expf(-(ir + hr)));
    float z = 1.f / (1.f + expf(-(iz + hz)));
    float n = tanhf(in_ + r * hn);
    size_t si = (size_t)m * KPAD + f;
    float h = __bfloat162float(hsp[si]) + __bfloat162float(hsp[APLANE + si]);
    float o = (1.f - z) * n + z * h;
    if (writeH) split2(o, &g_hsp[si], &g_hsp[APLANE + si]);
    float a = fmaxf(o, 0.f);
    split2(a, &g_asp[si], &g_asp[APLANE + si]);
}

__global__ __launch_bounds__(256) void attn_ctx_kernel(
    const float* __restrict__ sst, const int* __restrict__ deg)
{
    int bl = blockIdx.x;
    int b = bl >> 8;
    int tid = threadIdx.x;
    __shared__ int sidx[NNB];
    if (tid < NNB) sidx[tid] = deg[(size_t)bl * NNB + tid];
    __syncthreads();
    if (tid >= FF) return;
    int f = tid;
    float s1v = sst[(size_t)bl * F3 + f];
    float sc[NNB];
    float mx = -3.4e38f;
    #pragma unroll
    for (int n = 0; n < NNB; n++) {
        int j = sidx[n];
        float v = s1v + sst[((size_t)b * LL + j) * F3 + 200 + f];
        v = (v >= 0.f) ? v : 0.01f * v;
        if (j == LL - 1) v += -9e8f;
        sc[n] = v;
        mx = fmaxf(mx, v);
    }
    float sum = 0.f;
    #pragma unroll
    for (int n = 0; n < NNB; n++) { sc[n] = expf(sc[n] - mx); sum += sc[n]; }
    float inv = 1.f / sum;
    float c = 0.f;
    #pragma unroll
    for (int n = 0; n < NNB; n++) {
        int j = sidx[n];
        if (j != LL - 1)
            c += sc[n] * inv * sst[((size_t)b * LL + j) * F3 + 400 + f];
    }
    c = (c > 0.f) ? c : expm1f(c);
    size_t si = (size_t)bl * KPAD + f;
    split2(c, &g_csp[si], &g_csp[APLANE + si]);
}

__device__ __forceinline__ void seg_softmax_acc(const float* v, float* y, int lo, int hi) {
    float m = -3.4e38f;
    for (int i = lo; i < hi; i++) m = fmaxf(m, v[i]);
    float s = 0.f;
    for (int i = lo; i < hi; i++) s += expf(v[i] - m);
    float inv = 1.f / s;
    for (int i = lo; i < hi; i++) y[i] += expf(v[i] - m) * inv;
}
__device__ __forceinline__ float sigf(float x) { return 1.f / (1.f + expf(-x)); }

__global__ __launch_bounds__(256) void atom_act_kernel(
    const float* __restrict__ dec, float* __restrict__ out, int rows)
{
    int m = blockIdx.x * blockDim.x + threadIdx.x;
    if (m >= rows) return;
    const float* x = dec + (size_t)m * 64;
    float v[39], y[39];
    #pragma unroll
    for (int i = 0; i < 39; i++) { v[i] = x[i]; y[i] = 0.f; }
    seg_softmax_acc(v, y, 0, 16);
    seg_softmax_acc(v, y, 16, 22);
    seg_softmax_acc(v, y, 24, 30);
    seg_softmax_acc(v, y, 31, 36);
    y[24] += fmaxf(v[24], 0.f);
    y[30] += sigf(v[30]);
    y[36] += sigf(v[36]);
    y[37] += sigf(v[37]);
    y[38] += sigf(v[38]);
    float* o = out + (size_t)m * 39;
    #pragma unroll
    for (int i = 0; i < 39; i++) o[i] = y[i];
}

__global__ __launch_bounds__(256) void bond_act_kernel(
    const float* __restrict__ dec, const int* __restrict__ deg,
    float* __restrict__ out, int total)
{
    int id = blockIdx.x * blockDim.x + threadIdx.x;
    if (id >= total) return;
    int bl = id / NNB;
    int b = bl >> 8;
    int j = deg[id];
    const float* a = dec + (size_t)bl * 64 + 39;
    const float* c = dec + ((size_t)b * LL + j) * 64 + 49;
    float v[10], y[10];
    #pragma unroll
    for (int k = 0; k < 10; k++) { v[k] = a[k] + c[k]; y[k] = 0.f; }
    seg_softmax_acc(v, y, 0, 4);
    seg_softmax_acc(v, y, 6, 10);
    y[4] += sigf(v[4]);
    y[5] += sigf(v[5]);
    float* o = out + (size_t)id * 10;
    #pragma unroll
    for (int k = 0; k < 10; k++) o[k] = y[k];
}

static inline dim3 tg_grid(int M, int N, int z = 1) {
    return dim3((N + 127) / 128, M / 128, z);
}

extern "C" void kernel_launch(void* const* d_in, const int* in_sizes, int n_in,
                              void* d_out, int out_size)
{
    const int*   deg        = (const int*)  d_in[2];
    const float* molf       = (const float*)d_in[5];
    const float* actf       = (const float*)d_in[6];
    const float* atom_fc_w  = (const float*)d_in[7];
    const float* atom_fc_b  = (const float*)d_in[8];
    const float* bond_fc_w  = (const float*)d_in[9];
    const float* bond_fc_b  = (const float*)d_in[10];
    const float* align_w    = (const float*)d_in[11];
    const float* align_b    = (const float*)d_in[12];
    const float* attend_w   = (const float*)d_in[13];
    const float* attend_b   = (const float*)d_in[14];
    const float* gru_wih    = (const float*)d_in[15];
    const float* gru_whh    = (const float*)d_in[16];
    const float* gru_bih    = (const float*)d_in[17];
    const float* gru_bhh    = (const float*)d_in[18];
    const float* mol_al_w   = (const float*)d_in[19];
    const float* mol_al_b   = (const float*)d_in[20];
    const float* mgru_wih   = (const float*)d_in[21];
    const float* mgru_whh   = (const float*)d_in[22];
    const float* mgru_bih   = (const float*)d_in[23];
    const float* mgru_bhh   = (const float*)d_in[24];
    float* out = (float*)d_out;

    float *p_molW, *p_sst, *p_gi, *p_gh, *p_dec, *p_decb, *p_rb;
    __nv_bfloat16 *p_w, *p_h, *p_a, *p_c, *p_mf;
    cudaGetSymbolAddress((void**)&p_molW, g_molW);
    cudaGetSymbolAddress((void**)&p_sst,  g_sst);
    cudaGetSymbolAddress((void**)&p_gi,   g_gi);
    cudaGetSymbolAddress((void**)&p_gh,   g_gh);
    cudaGetSymbolAddress((void**)&p_dec,  g_dec);
    cudaGetSymbolAddress((void**)&p_decb, g_decb);
    cudaGetSymbolAddress((void**)&p_rb,   g_rb);
    cudaGetSymbolAddress((void**)&p_w,    g_wsp);
    cudaGetSymbolAddress((void**)&p_h,    g_hsp);
    cudaGetSymbolAddress((void**)&p_a,    g_asp);
    cudaGetSymbolAddress((void**)&p_c,    g_csp);
    cudaGetSymbolAddress((void**)&p_mf,   g_mfsp);

    cudaFuncSetAttribute(tgemm<0,0>, cudaFuncAttributeMaxDynamicSharedMemorySize, TG_SMEM);
    cudaFuncSetAttribute(tgemm<1,1>, cudaFuncAttributeMaxDynamicSharedMemorySize, TG_SMEM);

    const long AOB = (long)(APLANE * 2);
    const long MOB = (long)(MPLANE * 2);
    const long WOB = (long)(WPLANE * 2);

    // launch 0: bulk weight prep
    {
        PrepTab tab;
        int i = 0;
        auto add = [&](const float* s, int st, int dst) {
            tab.s[i].src = s; tab.s[i].stride = st; tab.s[i].dst = dst; tab.s[i].pad = 0; i++;
        };
        add(mol_al_w,      2*FF, W_MOL0);
        add(mol_al_w + FF, 2*FF, W_MOL1);
        add(mgru_wih,      FF,   W_MGI);
        add(mgru_whh,      FF,   W_MGH);
        for (int d = 0; d < RROUNDS; d++) {
            const float* aw = align_w + (size_t)d * FF * 2 * FF;
            add(aw,                             2*FF, W_RND(d) + 0);
            add(aw + FF,                        2*FF, W_RND(d) + 200);
            add(attend_w + (size_t)d * FF * FF, FF,   W_RND(d) + 400);
            add(gru_wih + (size_t)d * F3 * FF,  FF,   W_RND(d) + 600);
            add(gru_whh + (size_t)d * F3 * FF,  FF,   W_RND(d) + 1200);
        }
        prep_all<<<(W_DEC * KPAD + 255) / 256, 256>>>(tab);
    }
    // launch 1: all remaining prep
    prep_rest<<<(REST_TOT + 255) / 256, 256>>>(atom_fc_w, bond_fc_w,
                                               atom_fc_b, bond_fc_b,
                                               align_b, attend_b, molf);
    // launch 2
    mol_pre_kernel<<<BB, 256>>>(molf, actf);

    #define WOFFP(o) (p_w + (size_t)(o) * KPAD)
    #define NODUAL nullptr, nullptr, nullptr, nullptr

    // launch 3: molW (tiny)
    tgemm<0,0><<<tg_grid(BB, FF), 256, TG_SMEM>>>(
        p_mf, WOFFP(W_MOL0), mol_al_b, p_molW, nullptr,
        BB, FF, nullptr, 1, MOB, WOB, 0, NODUAL);

    for (int t = 0; t < TSTEPS; t++) {
        // launch 4 (first iter): ctx
        tgemm<1,1><<<tg_grid(BL, FF), 256, TG_SMEM>>>(
            p_h, WOFFP(W_MOL1), nullptr, nullptr, p_c,
            BL, FF, p_molW, LL, AOB, WOB, (long)APLANE, NODUAL);
        // launch 5 (first iter): dual gi+gh  <-- ncu -s 5 captures this
        tgemm<0,0><<<tg_grid(BL, F3, 2), 256, TG_SMEM>>>(
            p_c, WOFFP(W_MGI), mgru_bih, p_gi, nullptr,
            BL, F3, nullptr, 1, AOB, WOB, 0,
            p_h, WOFFP(W_MGH), mgru_bhh, p_gh);
        gru_combine_kernel<<<(BL * FF + 255) / 256, 256>>>(p_gi, p_gh, p_h, 1, BL * FF);
    }

    for (int d = 0; d < RROUNDS; d++) {
        tgemm<0,0><<<tg_grid(BL, F3), 256, TG_SMEM>>>(
            p_a, WOFFP(W_RND(d)), p_rb + (size_t)d * F3, p_sst, nullptr,
            BL, F3, nullptr, 1, AOB, WOB, 0, NODUAL);
        attn_ctx_kernel<<<BL, 256>>>(p_sst, deg);
        tgemm<0,0><<<tg_grid(BL, F3, 2), 256, TG_SMEM>>>(
            p_c, WOFFP(W_RND(d) + 600), gru_bih + (size_t)d * F3, p_gi, nullptr,
            BL, F3, nullptr, 1, AOB, WOB, 0,
            p_a, WOFFP(W_RND(d) + 1200), gru_bhh + (size_t)d * F3, p_gh);
        gru_combine_kernel<<<(BL * FF + 255) / 256, 256>>>(p_gi, p_gh, p_a, 0, BL * FF);
    }

    tgemm<0,0><<<tg_grid(BL, 64), 256, TG_SMEM>>>(
        p_a, WOFFP(W_DEC), p_decb, p_dec, nullptr,
        BL, 64, nullptr, 1, AOB, WOB, 0, NODUAL);

    atom_act_kernel<<<(BL + 255) / 256, 256>>>(p_dec, out, BL);
    bond_act_kernel<<<(BL * NNB + 255) / 256, 256>>>(p_dec, deg,
                                                     out + (size_t)BL * 39, BL * NNB);
}